// round 12
// baseline (speedup 1.0000x reference)
#include <cuda_runtime.h>
#include <cstddef>

// Problem constants (fixed by the reference: B=64, T=512, S=16, NZ=512)
#define BB 64
#define TT 512
#define SS 16
#define NZ 512

// Output layout (float32, concatenated flattened reference outputs):
//   cell_input      : [B, T, NZ]     at offset 0
//   reset_input     : [B, T, 2*NZ]   at offset B*T*NZ
//   reset_indicator : [B, T]         at offset B*T*3*NZ   (written as 0.0f / 1.0f)

// 256 threads per block; half-block h (=tid/128) handles timestep t0+h.
__global__ __launch_bounds__(2 * (NZ / 4), 6)
void soft2frames_kernel(const float* __restrict__ seg_start,  // [S, B]
                        const float* __restrict__ seg_end,    // [S, B]
                        const float* __restrict__ e0_seg,     // [S, B, NZ]
                        const float* __restrict__ eg_seg,     // [S, B, NZ]
                        float* __restrict__ out) {
    const int t0   = blockIdx.x * 2;          // first timestep of this block
    const int b    = blockIdx.y;              // 0..B-1
    const int tid  = threadIdx.x;             // 0..255
    const int h    = tid >> 7;                // half-block: 0 or 1
    const int htid = tid & 127;               // lane within half-block (float4 lane of NZ)
    const int t    = t0 + h;

    __shared__ int   sh_sel[2];
    __shared__ int   sh_ind[2];
    __shared__ float sh_inter[2];

    // ---- segment selection: warp 0 handles t0, warp 4 handles t0+1 ----
    if (htid < 32) {
        float ss = 0.f, se = 0.f;
        int inr = 0, hit = 0;
        if (htid < SS) {
            ss = __ldg(&seg_start[htid * BB + b]);   // 4 KB table, L1-broadcast
            se = __ldg(&seg_end[htid * BB + b]);
            const int cs = (int)ceilf(ss);
            const int fe = (int)floorf(se);
            inr = (t >= cs) & (t <= fe);
            hit = (min(max(cs, 0), TT - 1) == t);
        }
        const unsigned mc = __ballot_sync(0xffffffffu, inr);
        const unsigned mi = __ballot_sync(0xffffffffu, hit);
        const int sel = 31 - __clz(mc);            // last segment wins; -1 if uncovered
        const float st = __shfl_sync(0xffffffffu, ss, sel & 31);
        const float en = __shfl_sync(0xffffffffu, se, sel & 31);
        if (htid == 0) {
            sh_sel[h]   = sel;
            sh_ind[h]   = (mi != 0u);
            sh_inter[h] = ((float)t - st) / (en - st + 1e-7f);
        }
    }
    __syncthreads();

    const int   sel   = sh_sel[h];
    const float inter = sh_inter[h];

    const size_t bt = (size_t)b * TT + t;
    float* __restrict__ cellp = out + bt * NZ + htid * 4;
    float* __restrict__ rstp  = out + (size_t)BB * TT * NZ + bt * (2 * NZ) + htid * 4;

    if (sel >= 0) {
        const size_t base = ((size_t)sel * BB + b) * NZ;
        const float4 e = __ldg((const float4*)(e0_seg + base) + htid);
        const float4 g = __ldg((const float4*)(eg_seg + base) + htid);
        float4 c;
        c.x = fmaf(g.x - e.x, inter, e.x);
        c.y = fmaf(g.y - e.y, inter, e.y);
        c.z = fmaf(g.z - e.z, inter, e.z);
        c.w = fmaf(g.w - e.w, inter, e.w);
        __stcs((float4*)cellp, c);            // cell_input
        __stcs((float4*)rstp, g);             // reset_input[:, :NZ]  = e_gs
        __stcs((float4*)(rstp + NZ), e);      // reset_input[:, NZ:]  = e_0s
    } else {
        const float4 z = make_float4(0.f, 0.f, 0.f, 0.f);
        __stcs((float4*)cellp, z);
        __stcs((float4*)rstp, z);
        __stcs((float4*)(rstp + NZ), z);
    }

    if (htid == 0) {
        __stcs(out + (size_t)BB * TT * 3 * NZ + bt, (float)sh_ind[h]);  // reset_indicator
    }
}

extern "C" void kernel_launch(void* const* d_in, const int* in_sizes, int n_in,
                              void* d_out, int out_size) {
    const float* seg_start = (const float*)d_in[0];
    const float* seg_end   = (const float*)d_in[1];
    const float* e0_seg    = (const float*)d_in[2];
    const float* eg_seg    = (const float*)d_in[3];
    float* out = (float*)d_out;

    dim3 grid(TT / 2, BB);
    soft2frames_kernel<<<grid, 2 * (NZ / 4)>>>(seg_start, seg_end, e0_seg, eg_seg, out);
}

// round 13
// speedup vs baseline: 1.0009x; 1.0009x over previous
#include <cuda_runtime.h>
#include <cstddef>

// Problem constants (fixed by the reference: B=64, T=512, S=16, NZ=512)
#define BB 64
#define TT 512
#define SS 16
#define NZ 512

// Output layout (float32, concatenated flattened reference outputs):
//   cell_input      : [B, T, NZ]     at offset 0
//   reset_input     : [B, T, 2*NZ]   at offset B*T*NZ
//   reset_indicator : [B, T]         at offset B*T*3*NZ   (written as 0.0f / 1.0f)

__global__ __launch_bounds__(NZ / 4, 12)
void soft2frames_kernel(const float* __restrict__ seg_start,  // [S, B]
                        const float* __restrict__ seg_end,    // [S, B]
                        const float* __restrict__ e0_seg,     // [S, B, NZ]
                        const float* __restrict__ eg_seg,     // [S, B, NZ]
                        float* __restrict__ out) {
    const int t   = blockIdx.x;   // 0..T-1
    const int b   = blockIdx.y;   // 0..B-1
    const int tid = threadIdx.x;  // 0..127, one float4 lane of NZ

    __shared__ int   sh_sel;
    __shared__ int   sh_ind;
    __shared__ float sh_inter;

    // ---- segment selection: one warp, one lane per segment ----
    if (tid < 32) {
        float ss = 0.f, se = 0.f;
        int inr = 0, hit = 0;
        if (tid < SS) {
            ss = __ldg(&seg_start[tid * BB + b]);
            se = __ldg(&seg_end[tid * BB + b]);
            const int cs = (int)ceilf(ss);
            const int fe = (int)floorf(se);
            inr = (t >= cs) & (t <= fe);
            hit = (min(max(cs, 0), TT - 1) == t);
        }
        const unsigned mc = __ballot_sync(0xffffffffu, inr);
        const unsigned mi = __ballot_sync(0xffffffffu, hit);
        const int sel = 31 - __clz(mc);            // last segment wins; -1 if uncovered
        const float st = __shfl_sync(0xffffffffu, ss, sel & 31);
        const float en = __shfl_sync(0xffffffffu, se, sel & 31);
        if (tid == 0) {
            sh_sel   = sel;
            sh_ind   = (mi != 0u);
            sh_inter = ((float)t - st) / (en - st + 1e-7f);
        }
    }
    __syncthreads();

    const int   sel   = sh_sel;
    const float inter = sh_inter;

    const size_t bt = (size_t)b * TT + t;
    float* __restrict__ cellp = out + bt * NZ + tid * 4;
    float* __restrict__ rstp  = out + (size_t)BB * TT * NZ + bt * (2 * NZ) + tid * 4;

    if (sel >= 0) {
        const size_t base = ((size_t)sel * BB + b) * NZ;
        const float4 e = __ldg((const float4*)(e0_seg + base) + tid);
        const float4 g = __ldg((const float4*)(eg_seg + base) + tid);
        float4 c;
        c.x = fmaf(g.x - e.x, inter, e.x);
        c.y = fmaf(g.y - e.y, inter, e.y);
        c.z = fmaf(g.z - e.z, inter, e.z);
        c.w = fmaf(g.w - e.w, inter, e.w);
        __stcs((float4*)cellp, c);            // cell_input
        __stcs((float4*)rstp, g);             // reset_input[:, :NZ]  = e_gs
        __stcs((float4*)(rstp + NZ), e);      // reset_input[:, NZ:]  = e_0s
    } else {
        const float4 z = make_float4(0.f, 0.f, 0.f, 0.f);
        __stcs((float4*)cellp, z);
        __stcs((float4*)rstp, z);
        __stcs((float4*)(rstp + NZ), z);
    }

    if (tid == 0) {
        __stcs(out + (size_t)BB * TT * 3 * NZ + bt, (float)sh_ind);  // reset_indicator
    }
}

extern "C" void kernel_launch(void* const* d_in, const int* in_sizes, int n_in,
                              void* d_out, int out_size) {
    const float* seg_start = (const float*)d_in[0];
    const float* seg_end   = (const float*)d_in[1];
    const float* e0_seg    = (const float*)d_in[2];
    const float* eg_seg    = (const float*)d_in[3];
    float* out = (float*)d_out;

    dim3 grid(TT, BB);
    soft2frames_kernel<<<grid, NZ / 4>>>(seg_start, seg_end, e0_seg, eg_seg, out);
}